// round 1
// baseline (speedup 1.0000x reference)
#include <cuda_runtime.h>
#include <cuda_bf16.h>

// Problem constants
#define B_   8
#define C_   64
#define HW_  4096      // N = H*W
#define D_   8         // q/k projection dim

// Scratch (allocation-free rule: __device__ globals)
__device__ float g_q[B_ * HW_ * D_];    // [b][n][d]   1 MB
__device__ float g_k[B_ * HW_ * D_];    // [b][m][d]   1 MB
__device__ float g_v[B_ * HW_ * C_];    // [b][m][c]   8 MB (transposed proj_v)

// ---------------- packed f32x2 helpers ----------------
__device__ __forceinline__ unsigned long long fma2(unsigned long long a,
                                                   unsigned long long b,
                                                   unsigned long long c) {
    unsigned long long d;
    asm("fma.rn.f32x2 %0, %1, %2, %3;" : "=l"(d) : "l"(a), "l"(b), "l"(c));
    return d;
}
__device__ __forceinline__ unsigned long long pack2(float lo, float hi) {
    unsigned long long d;
    asm("mov.b64 %0, {%1, %2};" : "=l"(d) : "f"(lo), "f"(hi));
    return d;
}
__device__ __forceinline__ void unpack2(unsigned long long v, float& lo, float& hi) {
    asm("mov.b64 {%0, %1}, %2;" : "=f"(lo), "=f"(hi) : "l"(v));
}

// ---------------- Kernel 1: 1x1-conv projections ----------------
// q = Wq@query+bq, k = Wk@query+bk, v = Wv@value+bv, written transposed:
// g_q[b][n][d], g_k[b][m][d], g_v[b][m][c].
__global__ __launch_bounds__(256) void proj_kernel(
    const float* __restrict__ query, const float* __restrict__ value,
    const float* __restrict__ Wq, const float* __restrict__ bq,
    const float* __restrict__ Wk, const float* __restrict__ bk,
    const float* __restrict__ Wv, const float* __restrict__ bv) {
    __shared__ float sWq[D_ * C_];
    __shared__ float sWk[D_ * C_];
    __shared__ float sWv[C_ * C_];
    __shared__ float sbq[D_], sbk[D_], sbv[C_];

    const int tid = threadIdx.x;
    for (int i = tid; i < D_ * C_; i += 256) { sWq[i] = Wq[i]; sWk[i] = Wk[i]; }
    for (int i = tid; i < C_ * C_; i += 256) sWv[i] = Wv[i];
    if (tid < C_) sbv[tid] = bv[tid];
    if (tid < D_) { sbq[tid] = bq[tid]; sbk[tid] = bk[tid]; }
    __syncthreads();

    const int b = blockIdx.y;
    const int n = blockIdx.x * 256 + tid;

    const float* qbase = query + (size_t)b * C_ * HW_ + n;
    const float* vbase = value + (size_t)b * C_ * HW_ + n;

    float qa[D_], ka[D_], va[C_];
#pragma unroll
    for (int d = 0; d < D_; ++d) { qa[d] = 0.f; ka[d] = 0.f; }
#pragma unroll
    for (int o = 0; o < C_; ++o) va[o] = 0.f;

    for (int c = 0; c < C_; ++c) {
        const float x = qbase[(size_t)c * HW_];   // coalesced across tid
        const float y = vbase[(size_t)c * HW_];
#pragma unroll
        for (int d = 0; d < D_; ++d) {
            qa[d] += sWq[d * C_ + c] * x;
            ka[d] += sWk[d * C_ + c] * x;
        }
#pragma unroll
        for (int o = 0; o < C_; ++o) va[o] += sWv[o * C_ + c] * y;
    }

    const size_t row = (size_t)b * HW_ + n;
#pragma unroll
    for (int d = 0; d < D_; ++d) {
        g_q[row * D_ + d] = qa[d] + sbq[d];
        g_k[row * D_ + d] = ka[d] + sbk[d];
    }
#pragma unroll
    for (int o = 0; o < C_; ++o) g_v[row * C_ + o] = va[o] + sbv[o];
}

// ---------------- Kernel 2: fused attention ----------------
// Each thread owns one query row n: streams all m, p = exp(q.k), acc += p*v[m,:],
// denom += p, epilogue out[b][c][n] = acc[c]/denom + value[b][c][n].
// No max-subtraction needed: logits are O(10), exp fits fp32 comfortably.
#define MTILE 64
__global__ __launch_bounds__(256) void attn_kernel(
    const float* __restrict__ value, float* __restrict__ out) {
    __shared__ __align__(16) float k_sm[MTILE][D_];   // 2 KB
    __shared__ __align__(16) float v_sm[MTILE][C_];   // 16 KB

    const int tid = threadIdx.x;
    const int b = blockIdx.y;
    const int n = blockIdx.x * 256 + tid;

    const size_t qoff = ((size_t)b * HW_ + n) * D_;
    const float4 q0 = *(const float4*)&g_q[qoff];
    const float4 q1 = *(const float4*)&g_q[qoff + 4];

    unsigned long long acc2[C_ / 2];
#pragma unroll
    for (int i = 0; i < C_ / 2; ++i) acc2[i] = 0ULL;  // (0.f,0.f)
    float denom = 0.f;

    const float* kbase = g_k + (size_t)b * HW_ * D_;
    const float* vbase = g_v + (size_t)b * HW_ * C_;

    for (int t = 0; t < HW_ / MTILE; ++t) {
        __syncthreads();  // protect previous tile consumption
        // cooperative tile loads (coalesced float4)
        if (tid < (MTILE * D_) / 4)
            ((float4*)k_sm)[tid] = ((const float4*)(kbase + t * MTILE * D_))[tid];
        const float4* vsrc = (const float4*)(vbase + (size_t)t * MTILE * C_);
        float4* vdst = (float4*)v_sm;
#pragma unroll
        for (int j = 0; j < 4; ++j) vdst[tid + 256 * j] = vsrc[tid + 256 * j];
        __syncthreads();

#pragma unroll 4
        for (int mm = 0; mm < MTILE; ++mm) {
            const float4 k0 = *(const float4*)&k_sm[mm][0];
            const float4 k1 = *(const float4*)&k_sm[mm][4];
            float e = q0.x * k0.x + q0.y * k0.y + q0.z * k0.z + q0.w * k0.w +
                      q1.x * k1.x + q1.y * k1.y + q1.z * k1.z + q1.w * k1.w;
            const float p = __expf(e);
            denom += p;
            const unsigned long long p2 = pack2(p, p);
            const unsigned long long* vrow =
                (const unsigned long long*)&v_sm[mm][0];
#pragma unroll
            for (int i = 0; i < C_ / 2; ++i) acc2[i] = fma2(vrow[i], p2, acc2[i]);
        }
    }

    // epilogue: out = acc/denom + residual(value). Coalesced per-channel.
    const float inv = 1.0f / denom;
    const float* vres = value + (size_t)b * C_ * HW_ + n;
    float* obase = out + (size_t)b * C_ * HW_ + n;
#pragma unroll
    for (int i = 0; i < C_ / 2; ++i) {
        float lo, hi;
        unpack2(acc2[i], lo, hi);
        obase[(size_t)(2 * i) * HW_]     = lo * inv + vres[(size_t)(2 * i) * HW_];
        obase[(size_t)(2 * i + 1) * HW_] = hi * inv + vres[(size_t)(2 * i + 1) * HW_];
    }
}

extern "C" void kernel_launch(void* const* d_in, const int* in_sizes, int n_in,
                              void* d_out, int out_size) {
    const float* query = (const float*)d_in[0];
    const float* value = (const float*)d_in[1];
    const float* Wq    = (const float*)d_in[2];
    const float* bq    = (const float*)d_in[3];
    const float* Wk    = (const float*)d_in[4];
    const float* bk    = (const float*)d_in[5];
    const float* Wv    = (const float*)d_in[6];
    const float* bv    = (const float*)d_in[7];
    float* out = (float*)d_out;

    dim3 grid(HW_ / 256, B_);
    proj_kernel<<<grid, 256>>>(query, value, Wq, bq, Wk, bk, Wv, bv);
    attn_kernel<<<grid, 256>>>(value, out);
}

// round 3
// speedup vs baseline: 4.8655x; 4.8655x over previous
#include <cuda_runtime.h>
#include <cstdint>

#define B_   8
#define C_   64
#define HW_  4096
#define D_   8
#define TBN  128             // keys per tile
#define NT   (HW_ / TBN)     // 32
#define LOG2E 1.4426950408889634f

// ---------------- device scratch (allocation-free rule) ----------------
__device__ float g_q[B_ * HW_ * D_];   // [b][n][8], pre-scaled by log2e
__device__ float g_k[B_ * HW_ * D_];   // [b][m][8]
__device__ float g_v[B_ * C_ * HW_];   // [b][c][n]  channel-major

// ---------------- smem geometry (attn) ----------------
#define KPITCH  48                    // bytes per key row (12 floats, conflict-free)
#define KBYTES  (TBN * KPITCH)        // 6144
#define VPITCHB 528                   // bytes per chan row (132 floats, conflict-free)
#define VBYTES  (C_ * VPITCHB)        // 33792
#define BUFSZ   (KBYTES + VBYTES)     // 39936
#define SMEM_TOTAL (3 * BUFSZ)        // 119808

// ---------------- helpers ----------------
__device__ __forceinline__ uint32_t smem_u32(const void* p) {
    uint32_t a;
    asm("{ .reg .u64 t; cvta.to.shared.u64 t, %1; cvt.u32.u64 %0, t; }" : "=r"(a) : "l"(p));
    return a;
}
__device__ __forceinline__ float ex2f(float x) {
    float r; asm("ex2.approx.f32 %0, %1;" : "=f"(r) : "f"(x)); return r;
}
__device__ __forceinline__ uint32_t tf32r(float f) {   // round-to-nearest tf32 bits
    uint32_t u; asm("cvt.rna.tf32.f32 %0, %1;" : "=r"(u) : "f"(f)); return u;
}
__device__ __forceinline__ float lds32(uint32_t a) {
    float v; asm volatile("ld.shared.f32 %0, [%1];" : "=f"(v) : "r"(a)); return v;
}
__device__ __forceinline__ void cp16(uint32_t dst, const void* src) {
    asm volatile("cp.async.cg.shared.global [%0], [%1], 16;" :: "r"(dst), "l"(src) : "memory");
}
__device__ __forceinline__ void cp_commit() {
    asm volatile("cp.async.commit_group;" ::: "memory");
}
template <int N>
__device__ __forceinline__ void cp_wait() {
    asm volatile("cp.async.wait_group %0;" :: "n"(N) : "memory");
}
// m16n8k8 row.col f32 += tf32*tf32
__device__ __forceinline__ void mma8(float* c, const uint32_t* a, uint32_t b0, uint32_t b1) {
    asm("mma.sync.aligned.m16n8k8.row.col.f32.tf32.tf32.f32 "
        "{%0,%1,%2,%3},{%4,%5,%6,%7},{%8,%9},{%0,%1,%2,%3};"
        : "+f"(c[0]), "+f"(c[1]), "+f"(c[2]), "+f"(c[3])
        : "r"(a[0]), "r"(a[1]), "r"(a[2]), "r"(a[3]), "r"(b0), "r"(b1));
}

// ---------------- packed f32x2 helpers (proj) ----------------
__device__ __forceinline__ unsigned long long fma2(unsigned long long a,
                                                   unsigned long long b,
                                                   unsigned long long c) {
    unsigned long long d;
    asm("fma.rn.f32x2 %0, %1, %2, %3;" : "=l"(d) : "l"(a), "l"(b), "l"(c));
    return d;
}
__device__ __forceinline__ unsigned long long pack2(float lo, float hi) {
    unsigned long long d;
    asm("mov.b64 %0, {%1, %2};" : "=l"(d) : "f"(lo), "f"(hi));
    return d;
}
__device__ __forceinline__ void unpack2(unsigned long long v, float& lo, float& hi) {
    asm("mov.b64 {%0, %1}, %2;" : "=f"(lo), "=f"(hi) : "l"(v));
}

// ---------------- Kernel 1: 1x1-conv projections ----------------
__global__ __launch_bounds__(256) void proj_kernel(
    const float* __restrict__ query, const float* __restrict__ value,
    const float* __restrict__ Wq, const float* __restrict__ bq,
    const float* __restrict__ Wk, const float* __restrict__ bk,
    const float* __restrict__ Wv, const float* __restrict__ bv) {
    __shared__ __align__(16) float sWqT[C_ * D_];
    __shared__ __align__(16) float sWkT[C_ * D_];
    __shared__ __align__(16) float sWvT[C_ * C_];
    __shared__ float sbq[D_], sbk[D_], sbv[C_];

    const int tid = threadIdx.x;
    for (int i = tid; i < D_ * C_; i += 256) {
        int o = i / C_, c = i % C_;
        sWqT[c * D_ + o] = Wq[i];
        sWkT[c * D_ + o] = Wk[i];
    }
    for (int i = tid; i < C_ * C_; i += 256) {
        int o = i / C_, c = i % C_;
        sWvT[c * C_ + o] = Wv[i];
    }
    if (tid < C_) sbv[tid] = bv[tid];
    if (tid < D_) { sbq[tid] = bq[tid]; sbk[tid] = bk[tid]; }
    __syncthreads();

    const int b = blockIdx.y;
    const int n = blockIdx.x * 256 + tid;
    const float* qbase = query + (size_t)b * C_ * HW_ + n;
    const float* vbase = value + (size_t)b * C_ * HW_ + n;

    float qa[D_], ka[D_];
    unsigned long long va2[C_ / 2];
#pragma unroll
    for (int d = 0; d < D_; ++d) { qa[d] = 0.f; ka[d] = 0.f; }
#pragma unroll
    for (int i = 0; i < C_ / 2; ++i) va2[i] = 0ULL;

#pragma unroll 2
    for (int c = 0; c < C_; ++c) {
        const float x = qbase[(size_t)c * HW_];
        const float y = vbase[(size_t)c * HW_];
        const float4 wq  = *(const float4*)&sWqT[c * D_];
        const float4 wq2 = *(const float4*)&sWqT[c * D_ + 4];
        const float4 wk  = *(const float4*)&sWkT[c * D_];
        const float4 wk2 = *(const float4*)&sWkT[c * D_ + 4];
        qa[0] += wq.x * x;  qa[1] += wq.y * x;  qa[2] += wq.z * x;  qa[3] += wq.w * x;
        qa[4] += wq2.x * x; qa[5] += wq2.y * x; qa[6] += wq2.z * x; qa[7] += wq2.w * x;
        ka[0] += wk.x * x;  ka[1] += wk.y * x;  ka[2] += wk.z * x;  ka[3] += wk.w * x;
        ka[4] += wk2.x * x; ka[5] += wk2.y * x; ka[6] += wk2.z * x; ka[7] += wk2.w * x;
        const unsigned long long y2 = pack2(y, y);
        const ulonglong2* wv = (const ulonglong2*)&sWvT[c * C_];
#pragma unroll
        for (int i = 0; i < C_ / 4; ++i) {
            ulonglong2 w = wv[i];
            va2[2 * i]     = fma2(w.x, y2, va2[2 * i]);
            va2[2 * i + 1] = fma2(w.y, y2, va2[2 * i + 1]);
        }
    }

    const size_t row = (size_t)b * HW_ + n;
    // vectorized q/k writes (32B per thread, coalesced)
    *(float4*)&g_q[row * D_] = make_float4(
        (qa[0] + sbq[0]) * LOG2E, (qa[1] + sbq[1]) * LOG2E,
        (qa[2] + sbq[2]) * LOG2E, (qa[3] + sbq[3]) * LOG2E);
    *(float4*)&g_q[row * D_ + 4] = make_float4(
        (qa[4] + sbq[4]) * LOG2E, (qa[5] + sbq[5]) * LOG2E,
        (qa[6] + sbq[6]) * LOG2E, (qa[7] + sbq[7]) * LOG2E);
    *(float4*)&g_k[row * D_] = make_float4(
        ka[0] + sbk[0], ka[1] + sbk[1], ka[2] + sbk[2], ka[3] + sbk[3]);
    *(float4*)&g_k[row * D_ + 4] = make_float4(
        ka[4] + sbk[4], ka[5] + sbk[5], ka[6] + sbk[6], ka[7] + sbk[7]);

    float* vout = g_v + (size_t)b * C_ * HW_ + n;
#pragma unroll
    for (int i = 0; i < C_ / 2; ++i) {
        float lo, hi;
        unpack2(va2[i], lo, hi);
        vout[(size_t)(2 * i) * HW_]     = lo + sbv[2 * i];
        vout[(size_t)(2 * i + 1) * HW_] = hi + sbv[2 * i + 1];
    }
}

// ---------------- tile loader (all 256 threads) ----------------
__device__ __forceinline__ void load_tile(uint32_t smb, int buf, int b, int m0, int tid) {
    const uint32_t base = smb + buf * BUFSZ;
    // K: 128 keys x 32B, padded to 48B rows.  tid -> key tid>>1, half tid&1
    {
        const float* ksrc = g_k + ((size_t)b * HW_ + m0) * D_ + tid * 4;
        uint32_t kdst = base + (tid >> 1) * KPITCH + (tid & 1) * 16;
        cp16(kdst, ksrc);
    }
    // V: 64 chans x 512B, padded to 528B rows
    const uint32_t vb = base + KBYTES;
    const float* vsrcb = g_v + (size_t)b * C_ * HW_ + m0;
#pragma unroll
    for (int r = 0; r < 8; ++r) {
        int idx = tid + 256 * r;
        int ch = idx >> 5, sg = idx & 31;
        cp16(vb + ch * VPITCHB + sg * 16, vsrcb + (size_t)ch * HW_ + sg * 4);
    }
}

// ---------------- Kernel 2: mma.sync tf32 flash attention ----------------
// CTA: 256 threads, 8 warps x 32 query rows = 256 rows.  Grid: (16, 8).
__global__ __launch_bounds__(256, 1) void attn_kernel(
    const float* __restrict__ value, float* __restrict__ out) {
    extern __shared__ char sm[];
    const uint32_t smb = smem_u32(sm);
    const int tid = threadIdx.x;
    const int w = tid >> 5;
    const int lane = tid & 31;
    const int g = lane >> 2;           // group 0..7
    const int tg = lane & 3;           // thread-in-group 0..3
    const int b = blockIdx.y;
    const int n0 = blockIdx.x * 256;

    // prologue: prefetch tiles 0,1
    load_tile(smb, 0, b, 0, tid);
    cp_commit();
    load_tile(smb, 1, b, TBN, tid);
    cp_commit();

    // Q fragments (A-frag layout), rounded to tf32
    const int rbase = n0 + w * 32 + g;
    uint32_t qa[2][4];
#pragma unroll
    for (int mt = 0; mt < 2; ++mt) {
        const float* q0 = g_q + ((size_t)b * HW_ + rbase + 16 * mt) * D_;
        const float* q1 = q0 + 8 * D_;   // row +8
        qa[mt][0] = tf32r(q0[tg]);
        qa[mt][1] = tf32r(q1[tg]);
        qa[mt][2] = tf32r(q0[tg + 4]);
        qa[mt][3] = tf32r(q1[tg + 4]);
    }

    float o[2][8][4];
#pragma unroll
    for (int mt = 0; mt < 2; ++mt)
#pragma unroll
        for (int ct = 0; ct < 8; ++ct)
#pragma unroll
            for (int i = 0; i < 4; ++i) o[mt][ct][i] = 0.f;
    float rs[4] = {0.f, 0.f, 0.f, 0.f};

    // key permutation kappa(g) = (g>>1) + 4*(g&1): makes S C-frag == PV A-frag
    const int kap = (g >> 1) + ((g & 1) << 2);

    for (int t = 0; t < NT; ++t) {
        cp_wait<1>();
        __syncthreads();
        if (t + 2 < NT) load_tile(smb, (t + 2) % 3, b, (t + 2) * TBN, tid);
        cp_commit();

        const uint32_t base = smb + (t % 3) * BUFSZ;
        const uint32_t kbase = base + kap * KPITCH + tg * 4;
        const uint32_t vbase = base + KBYTES + g * VPITCHB + tg * 4;

#pragma unroll 4
        for (int j = 0; j < 16; ++j) {
            // K B-frag (permuted keys)
            const uint32_t ka0 = __float_as_uint(lds32(kbase + j * 8 * KPITCH));
            const uint32_t ka1 = __float_as_uint(lds32(kbase + j * 8 * KPITCH + 16));
            // S = Q.K^T for both m-tiles
            float s0[4] = {0.f, 0.f, 0.f, 0.f};
            float s1[4] = {0.f, 0.f, 0.f, 0.f};
            mma8(s0, qa[0], ka0, ka1);
            mma8(s1, qa[1], ka0, ka1);
            // exp2 -> tf32 round -> denom (post-round, bias cancels) -> A-frags
            uint32_t a0[4], a1[4];
            {
                uint32_t u0 = tf32r(ex2f(s0[0])), u1 = tf32r(ex2f(s0[1]));
                uint32_t u2 = tf32r(ex2f(s0[2])), u3 = tf32r(ex2f(s0[3]));
                rs[0] += __uint_as_float(u0) + __uint_as_float(u1);
                rs[1] += __uint_as_float(u2) + __uint_as_float(u3);
                a0[0] = u0; a0[1] = u2; a0[2] = u1; a0[3] = u3;
            }
            {
                uint32_t u0 = tf32r(ex2f(s1[0])), u1 = tf32r(ex2f(s1[1]));
                uint32_t u2 = tf32r(ex2f(s1[2])), u3 = tf32r(ex2f(s1[3]));
                rs[2] += __uint_as_float(u0) + __uint_as_float(u1);
                rs[3] += __uint_as_float(u2) + __uint_as_float(u3);
                a1[0] = u0; a1[1] = u2; a1[2] = u1; a1[3] = u3;
            }
            // O += P.V  (8 chan-tiles, B-frags shared across the 2 m-tiles)
#pragma unroll
            for (int ct = 0; ct < 8; ++ct) {
                const uint32_t va = vbase + ct * 8 * VPITCHB + j * 32;
                const uint32_t vb0 = __float_as_uint(lds32(va));
                const uint32_t vb1 = __float_as_uint(lds32(va + 16));
                mma8(o[0][ct], a0, vb0, vb1);
                mma8(o[1][ct], a1, vb0, vb1);
            }
        }
    }

    // row-sum reduce across the 4 tg-lanes, then epilogue
#pragma unroll
    for (int i = 0; i < 4; ++i) {
        rs[i] += __shfl_xor_sync(0xffffffffu, rs[i], 1);
        rs[i] += __shfl_xor_sync(0xffffffffu, rs[i], 2);
    }
    float inv[4];
#pragma unroll
    for (int i = 0; i < 4; ++i) inv[i] = 1.0f / rs[i];

    const float* vres = value + (size_t)b * C_ * HW_;
    float* ob = out + (size_t)b * C_ * HW_;
#pragma unroll
    for (int mt = 0; mt < 2; ++mt) {
        const int r0 = rbase + 16 * mt;
#pragma unroll
        for (int ct = 0; ct < 8; ++ct) {
            const int ch = ct * 8 + 2 * tg;
            const size_t i00 = (size_t)ch * HW_ + r0;        // (ch,   r0)
            const size_t i01 = i00 + HW_;                    // (ch+1, r0)
            const size_t i10 = i00 + 8;                      // (ch,   r0+8)
            const size_t i11 = i01 + 8;                      // (ch+1, r0+8)
            ob[i00] = o[mt][ct][0] * inv[2 * mt]     + vres[i00];
            ob[i01] = o[mt][ct][1] * inv[2 * mt]     + vres[i01];
            ob[i10] = o[mt][ct][2] * inv[2 * mt + 1] + vres[i10];
            ob[i11] = o[mt][ct][3] * inv[2 * mt + 1] + vres[i11];
        }
    }
}

extern "C" void kernel_launch(void* const* d_in, const int* in_sizes, int n_in,
                              void* d_out, int out_size) {
    const float* query = (const float*)d_in[0];
    const float* value = (const float*)d_in[1];
    const float* Wq    = (const float*)d_in[2];
    const float* bq    = (const float*)d_in[3];
    const float* Wk    = (const float*)d_in[4];
    const float* bk    = (const float*)d_in[5];
    const float* Wv    = (const float*)d_in[6];
    const float* bv    = (const float*)d_in[7];
    float* out = (float*)d_out;

    cudaFuncSetAttribute(attn_kernel, cudaFuncAttributeMaxDynamicSharedMemorySize,
                         SMEM_TOTAL);

    dim3 pgrid(HW_ / 256, B_);
    proj_kernel<<<pgrid, 256>>>(query, value, Wq, bq, Wk, bk, Wv, bv);
    dim3 agrid(HW_ / 256, B_);
    attn_kernel<<<agrid, 256, SMEM_TOTAL>>>(value, out);
}